// round 16
// baseline (speedup 1.0000x reference)
#include <cuda_runtime.h>
#include <cuda_fp16.h>
#include <math.h>
#include <stdint.h>

#define BSZ 32
#define LEN 8192
#define ROWS (BSZ*LEN)
#define NTILES (ROWS/128)    // 2048 tiles of 128 rows
#define MUGRID 148

// fp16-element strides (all == 4 mod 32 words -> conflict-free)
#define S1 136
#define S2 264
#define SQ 72
// smem byte offsets
#define OW2  69632
#define OWQ  103424
#define OPX  112640
#define OPH  147456
#define OB1  215040
#define OB2  216064
#define OBQ  216320
#define SMEM_MU 216576

__device__ float g_mu[(size_t)ROWS * 64];
__device__ float g_epart[BSZ * 128];

// ---------------------------------------------------------------------------
__device__ __forceinline__ void mma16816h(float* c, const uint32_t* a,
                                          uint32_t b0, uint32_t b1)
{
    asm volatile(
        "mma.sync.aligned.m16n8k16.row.col.f32.f16.f16.f32 "
        "{%0,%1,%2,%3},{%4,%5,%6,%7},{%8,%9},{%0,%1,%2,%3};\n"
        : "+f"(c[0]), "+f"(c[1]), "+f"(c[2]), "+f"(c[3])
        : "r"(a[0]), "r"(a[1]), "r"(a[2]), "r"(a[3]), "r"(b0), "r"(b1));
}

__device__ __forceinline__ void ldsm4(uint32_t* d, uint32_t addr)
{
    asm volatile("ldmatrix.sync.aligned.m8n8.x4.shared.b16 {%0,%1,%2,%3}, [%4];"
        : "=r"(d[0]), "=r"(d[1]), "=r"(d[2]), "=r"(d[3]) : "r"(addr));
}

__device__ __forceinline__ uint32_t pack2h(float x0, float x1)
{
    __half2 h = __floats2half2_rn(x0, x1);
    return *(uint32_t*)&h;
}

__device__ __forceinline__ float tanh_fast(float x)
{
    float y;
    asm("tanh.approx.f32 %0, %1;" : "=f"(y) : "f"(x));
    return y;
}

__device__ __forceinline__ float softplus_fast(float m)
{
    return fmaxf(m, 0.f) + __logf(1.f + __expf(-fabsf(m)));
}

// ---------------------------------------------------------------------------
// Persistent mu kernel: 148 CTAs x 512 thr, 128-row tiles, fp16 MMA.
//   H = relu([A;B] @ W1h + b1); M = H @ W2h + b2; G = q @ Wqh + bq
//   mu = softplus(M) * (1 + 0.5*tanh(G))
// All stages: 4m x 4n warp grid. Stage1 warp = 32 rows x 64 cols;
// stage2/gate warp = 32 rows x 16 cols. B via ldmatrix.x4.
// Prefetch q during stage1; next X during stage2/gate.
// ---------------------------------------------------------------------------
__global__ void __launch_bounds__(512, 1) mu_kernel(
        const float* __restrict__ A, const float* __restrict__ Bm,
        const float* __restrict__ qp,
        const float* __restrict__ W1, const float* __restrict__ b1,
        const float* __restrict__ W2, const float* __restrict__ b2,
        const float* __restrict__ Wq, const float* __restrict__ bq)
{
    extern __shared__ char sm[];
    __half* sW1 = (__half*)sm;
    __half* sW2 = (__half*)(sm + OW2);
    __half* sWq = (__half*)(sm + OWQ);
    __half* pX  = (__half*)(sm + OPX);
    __half* pH  = (__half*)(sm + OPH);
    float* sB1 = (float*)(sm + OB1);
    float* sB2 = (float*)(sm + OB2);
    float* sBq = (float*)(sm + OBQ);

    const int tid = threadIdx.x, lane = tid & 31, wid = tid >> 5;
    const int wm = wid & 3, wn = wid >> 2;            // 4m x 4n (all stages)
    const int r = lane >> 2, c2 = lane & 3;
    const uint32_t smb = (uint32_t)__cvta_generic_to_shared(sm);

    // one-time fills (coalesced fp32 reads, fp16 convert)
    for (int i = tid; i < 256 * 128; i += 512) {
        int k = i >> 8, n = i & 255;                  // W1[k][n]
        sW1[n * S1 + k] = __float2half_rn(W1[i]);
    }
    for (int i = tid; i < 64 * 256; i += 512) {
        int k = i >> 6, n = i & 63;                   // W2[k][n]
        sW2[n * S2 + k] = __float2half_rn(W2[i]);
    }
    for (int i = tid; i < 64 * 64; i += 512) {
        int k = i >> 6, n = i & 63;                   // Wq[k][n]
        sWq[n * SQ + k] = __float2half_rn(Wq[i]);
    }
    if (tid < 256) sB1[tid] = b1[tid];
    if (tid < 64) { sB2[tid] = b2[tid]; sBq[tid] = bq[tid]; }
    __syncthreads();

    // ldmatrix lane->address components
    const int lrow = (lane & 7) + ((lane >> 3) & 1) * 8;   // A-frag pattern
    const int lk   = (lane >> 4) * 8;
    const int brow = (lane & 7) + ((lane >> 4) << 3);      // B-frag pattern
    const int bk   = ((lane >> 3) & 1) << 3;
    const uint32_t pXs = smb + OPX, pHs = smb + OPH;
    const uint32_t sW1s = smb, sW2s = smb + OW2, sWqs = smb + OWQ;

    const int oc = (wn << 4) + (c2 << 1);                  // stage2/gate col base
    float b2v[2][2], bqv[2][2];
#pragma unroll
    for (int nt = 0; nt < 2; nt++) {
        b2v[nt][0] = sB2[oc + (nt << 3)]; b2v[nt][1] = sB2[oc + (nt << 3) + 1];
        bqv[nt][0] = sBq[oc + (nt << 3)]; bqv[nt][1] = sBq[oc + (nt << 3) + 1];
    }
    float b1v[8][2];
#pragma unroll
    for (int nt = 0; nt < 8; nt++) {
        int n0 = (wn << 6) + (nt << 3) + (c2 << 1);
        b1v[nt][0] = sB1[n0]; b1v[nt][1] = sB1[n0 + 1];
    }

    // prologue: first tile's X packed to half2 (16 regs)
    uint32_t xr[16];
    {
        int t0 = blockIdx.x;
        if (t0 < NTILES) {
            const size_t row0 = (size_t)t0 * 128;
#pragma unroll
            for (int i = 0; i < 8; i++) {
                int e = i * 512 + tid;
                int row = e >> 5, kk = (e & 31) * 4;
                const float* src = (kk < 64) ? (A + (row0 + row) * 64 + kk)
                                             : (Bm + (row0 + row) * 64 + kk - 64);
                float4 v = *(const float4*)src;
                xr[2 * i]     = pack2h(v.x, v.y);
                xr[2 * i + 1] = pack2h(v.z, v.w);
            }
        }
    }

    for (int t = blockIdx.x; t < NTILES; t += gridDim.x) {
        const size_t row0 = (size_t)t * 128;

        // ---- store X plane (128 rows x 128 k) ----
#pragma unroll
        for (int i = 0; i < 8; i++) {
            int e = i * 512 + tid;
            int row = e >> 5, kk = (e & 31) * 4;
            *(uint2*)(pX + row * S1 + kk) = make_uint2(xr[2 * i], xr[2 * i + 1]);
        }
        __syncthreads();                                  // (a)

        // prefetch q (packed, 8 regs)
        uint32_t qr[8];
#pragma unroll
        for (int i = 0; i < 4; i++) {
            int e = i * 512 + tid;
            int row = e >> 4, kk = (e & 15) * 4;
            float4 v = *(const float4*)(qp + (row0 + row) * 64 + kk);
            qr[2 * i]     = pack2h(v.x, v.y);
            qr[2 * i + 1] = pack2h(v.z, v.w);
        }

        // ---- stage 1: acc = X @ W1h (warp: 32 rows x 64 cols) ----
        float acc[2][8][4];
#pragma unroll
        for (int mt = 0; mt < 2; mt++)
#pragma unroll
            for (int nt = 0; nt < 8; nt++)
#pragma unroll
                for (int i = 0; i < 4; i++) acc[mt][nt][i] = 0.f;
#pragma unroll
        for (int ks = 0; ks < 8; ks++) {
            const int k0 = ks * 16;
            uint32_t ah[2][4], bw[16];
#pragma unroll
            for (int mt = 0; mt < 2; mt++) {
                uint32_t off = (uint32_t)((((wm << 5) + 16 * mt + lrow) * S1 + k0 + lk) * 2);
                ldsm4(ah[mt], pXs + off);
            }
#pragma unroll
            for (int nb = 0; nb < 4; nb++)
                ldsm4(bw + 4 * nb,
                      sW1s + (uint32_t)((((wn << 6) + (nb << 4) + brow) * S1 + k0 + bk) * 2));
#pragma unroll
            for (int nt = 0; nt < 8; nt++)
#pragma unroll
                for (int mt = 0; mt < 2; mt++)
                    mma16816h(acc[mt][nt], ah[mt], bw[2 * nt], bw[2 * nt + 1]);
        }
        __syncthreads();                                  // (b)

        // ---- store H (relu+bias, fp16) + q into dead X plane ----
#pragma unroll
        for (int mt = 0; mt < 2; mt++)
#pragma unroll
            for (int nt = 0; nt < 8; nt++) {
                int cl = (wn << 6) + (nt << 3) + (c2 << 1);
                int rb = (wm << 5) + 16 * mt;
                float h0 = fmaxf(acc[mt][nt][0] + b1v[nt][0], 0.f);
                float h1 = fmaxf(acc[mt][nt][1] + b1v[nt][1], 0.f);
                *(uint32_t*)(pH + (rb + r) * S2 + cl) = pack2h(h0, h1);
                float h2 = fmaxf(acc[mt][nt][2] + b1v[nt][0], 0.f);
                float h3 = fmaxf(acc[mt][nt][3] + b1v[nt][1], 0.f);
                *(uint32_t*)(pH + (rb + 8 + r) * S2 + cl) = pack2h(h2, h3);
            }
#pragma unroll
        for (int i = 0; i < 4; i++) {
            int e = i * 512 + tid;
            int row = e >> 4, kk = (e & 15) * 4;
            *(uint2*)(pX + row * S1 + kk) = make_uint2(qr[2 * i], qr[2 * i + 1]);
        }

        // prefetch next tile's X (overlaps stage2/gate MMAs)
        {
            int tn = t + gridDim.x;
            if (tn < NTILES) {
                const size_t rown = (size_t)tn * 128;
#pragma unroll
                for (int i = 0; i < 8; i++) {
                    int e = i * 512 + tid;
                    int row = e >> 5, kk = (e & 31) * 4;
                    const float* src = (kk < 64) ? (A + (rown + row) * 64 + kk)
                                                 : (Bm + (rown + row) * 64 + kk - 64);
                    float4 v = *(const float4*)src;
                    xr[2 * i]     = pack2h(v.x, v.y);
                    xr[2 * i + 1] = pack2h(v.z, v.w);
                }
            }
        }
        __syncthreads();                                  // (c)

        // ---- stage 2: M = H @ W2h (warp: 32 rows x 16 cols, K=256) ----
        float acc2[2][2][4];
#pragma unroll
        for (int mt = 0; mt < 2; mt++)
#pragma unroll
            for (int nt = 0; nt < 2; nt++)
#pragma unroll
                for (int i = 0; i < 4; i++) acc2[mt][nt][i] = 0.f;
#pragma unroll
        for (int ks = 0; ks < 16; ks++) {
            const int k0 = ks * 16;
            uint32_t ah[2][4], bw[4];
#pragma unroll
            for (int mt = 0; mt < 2; mt++)
                ldsm4(ah[mt], pHs + (uint32_t)((((wm << 5) + 16 * mt + lrow) * S2 + k0 + lk) * 2));
            ldsm4(bw, sW2s + (uint32_t)((((wn << 4) + brow) * S2 + k0 + bk) * 2));
#pragma unroll
            for (int mt = 0; mt < 2; mt++) {
                mma16816h(acc2[mt][0], ah[mt], bw[0], bw[1]);
                mma16816h(acc2[mt][1], ah[mt], bw[2], bw[3]);
            }
        }

        // ---- gate: G = q @ Wqh (warp: 32 rows x 16 cols, K=64) ----
        float accg[2][2][4];
#pragma unroll
        for (int mt = 0; mt < 2; mt++)
#pragma unroll
            for (int nt = 0; nt < 2; nt++)
#pragma unroll
                for (int i = 0; i < 4; i++) accg[mt][nt][i] = 0.f;
#pragma unroll
        for (int ks = 0; ks < 4; ks++) {
            const int k0 = ks * 16;
            uint32_t ah[2][4], bw[4];
#pragma unroll
            for (int mt = 0; mt < 2; mt++)
                ldsm4(ah[mt], pXs + (uint32_t)((((wm << 5) + 16 * mt + lrow) * S1 + k0 + lk) * 2));
            ldsm4(bw, sWqs + (uint32_t)((((wn << 4) + brow) * SQ + k0 + bk) * 2));
#pragma unroll
            for (int mt = 0; mt < 2; mt++) {
                mma16816h(accg[mt][0], ah[mt], bw[0], bw[1]);
                mma16816h(accg[mt][1], ah[mt], bw[2], bw[3]);
            }
        }

        // ---- epilogue: mu = softplus(M+b2) * (1 + 0.5*tanh(G+bq)) ----
#pragma unroll
        for (int mt = 0; mt < 2; mt++)
#pragma unroll
            for (int nt = 0; nt < 2; nt++) {
                int col = oc + (nt << 3);
                int row = (wm << 5) + 16 * mt + r;
                float m0 = acc2[mt][nt][0] + b2v[nt][0], m1 = acc2[mt][nt][1] + b2v[nt][1];
                float g0 = tanh_fast(accg[mt][nt][0] + bqv[nt][0]);
                float g1 = tanh_fast(accg[mt][nt][1] + bqv[nt][1]);
                *(float2*)&g_mu[(row0 + row) * 64 + col] =
                    make_float2(softplus_fast(m0) * (1.f + 0.5f * g0),
                                softplus_fast(m1) * (1.f + 0.5f * g1));
                float m2 = acc2[mt][nt][2] + b2v[nt][0], m3 = acc2[mt][nt][3] + b2v[nt][1];
                float g2 = tanh_fast(accg[mt][nt][2] + bqv[nt][0]);
                float g3 = tanh_fast(accg[mt][nt][3] + bqv[nt][1]);
                *(float2*)&g_mu[(row0 + row + 8) * 64 + col] =
                    make_float2(softplus_fast(m2) * (1.f + 0.5f * g2),
                                softplus_fast(m3) * (1.f + 0.5f * g3));
            }
        __syncthreads();                                  // (d)
    }
}

// ---------------------------------------------------------------------------
// Iteration kernel: 10 rows/thread, TL=64 interior, halo 8, 2 blocks/SM.
// smooth(x)[l] = 0.9*x[l] + 0.05*(x[l-1]+x[l+1]);  D scaled by (1-0.3*mu).
// ---------------------------------------------------------------------------
__global__ void __launch_bounds__(512, 2) iter_kernel(
        const float* __restrict__ A, const float* __restrict__ Bm,
        float* __restrict__ hA, float* __restrict__ hB)
{
    __shared__ float sme[2][4][8][64];
    const int tid = threadIdx.x;
    const int c = tid & 63;
    const int j = tid >> 6;
    const int b = blockIdx.y;
    const int lbase = blockIdx.x * 64 - 8;
    const size_t base = ((size_t)b << 13);

    float D[10], S[10], MU[10];
#pragma unroll
    for (int rr = 0; rr < 10; rr++) {
        int l = (lbase + j * 10 + rr) & (LEN - 1);
        size_t g = (base + l) * 64 + c;
        float a = A[g], bb = Bm[g];
        D[rr] = a - bb;
        S[rr] = a + bb;
        MU[rr] = g_mu[g];
    }

#pragma unroll
    for (int k = 0; k < 6; k++) {
        const int p = k & 1;
        sme[p][0][j][c] = (1.f - 0.3f * MU[0]) * D[0];
        sme[p][1][j][c] = (1.f - 0.3f * MU[9]) * D[9];
        sme[p][2][j][c] = S[0];
        sme[p][3][j][c] = S[9];
        __syncthreads();
        float gylo = (j > 0) ? sme[p][1][j - 1][c] : 0.f;
        float gyhi = (j < 7) ? sme[p][0][j + 1][c] : 0.f;
        float gslo = (j > 0) ? sme[p][3][j - 1][c] : 0.f;
        float gshi = (j < 7) ? sme[p][2][j + 1][c] : 0.f;

        float yprev = gylo, sprev = gslo;
#pragma unroll
        for (int rr = 0; rr < 10; rr++) {
            float ycur  = (1.f - 0.3f * MU[rr]) * D[rr];
            float ynext = (rr < 9) ? (1.f - 0.3f * MU[rr + 1]) * D[rr + 1] : gyhi;
            float scur  = S[rr];
            float snext = (rr < 9) ? S[rr + 1] : gshi;
            D[rr] = 0.9f * ycur + 0.05f * (yprev + ynext);
            S[rr] = 0.9f * scur + 0.05f * (sprev + snext);
            yprev = ycur;
            sprev = scur;
        }
    }

    float esum = 0.f;
#pragma unroll
    for (int rr = 0; rr < 10; rr++) {
        int gidx = j * 10 + rr;
        if (gidx >= 8 && gidx < 72) {
            int l = blockIdx.x * 64 + (gidx - 8);
            size_t g = (base + l) * 64 + c;
            hA[g] = 0.5f * (S[rr] + D[rr]);
            hB[g] = 0.5f * (S[rr] - D[rr]);
            esum += 0.5f * MU[rr] * D[rr] * D[rr];
        }
    }

#pragma unroll
    for (int o = 16; o > 0; o >>= 1)
        esum += __shfl_xor_sync(0xffffffffu, esum, o);
    __shared__ float sred[16];
    if ((tid & 31) == 0) sred[tid >> 5] = esum;
    __syncthreads();
    if (tid == 0) {
        float tt = 0.f;
#pragma unroll
        for (int w = 0; w < 16; w++) tt += sred[w];
        g_epart[b * 128 + blockIdx.x] = tt;
    }
}

// ---------------------------------------------------------------------------
__global__ void __launch_bounds__(128) energy_reduce(float* __restrict__ energy)
{
    const int b = blockIdx.x;
    const int tid = threadIdx.x;
    float v = g_epart[b * 128 + tid];
#pragma unroll
    for (int o = 16; o > 0; o >>= 1)
        v += __shfl_xor_sync(0xffffffffu, v, o);
    __shared__ float s[4];
    if ((tid & 31) == 0) s[tid >> 5] = v;
    __syncthreads();
    if (tid == 0) energy[b] = s[0] + s[1] + s[2] + s[3];
}

// ---------------------------------------------------------------------------
extern "C" void kernel_launch(void* const* d_in, const int* in_sizes, int n_in,
                              void* d_out, int out_size)
{
    const float* A  = (const float*)d_in[0];
    const float* Bm = (const float*)d_in[1];
    const float* q  = (const float*)d_in[2];
    const float* W1 = (const float*)d_in[3];
    const float* b1 = (const float*)d_in[4];
    const float* W2 = (const float*)d_in[5];
    const float* b2 = (const float*)d_in[6];
    const float* Wq = (const float*)d_in[7];
    const float* bq = (const float*)d_in[8];

    float* out = (float*)d_out;
    float* hA = out;
    float* hB = out + (size_t)ROWS * 64;
    float* en = out + 2 * (size_t)ROWS * 64;

    static int attr_set = 0;
    if (!attr_set) {
        cudaFuncSetAttribute(mu_kernel,
            cudaFuncAttributeMaxDynamicSharedMemorySize, SMEM_MU);
        attr_set = 1;
    }
    mu_kernel<<<MUGRID, 512, SMEM_MU>>>(A, Bm, q, W1, b1, W2, b2, Wq, bq);

    iter_kernel<<<dim3(LEN / 64, BSZ), 512>>>(A, Bm, hA, hB);

    energy_reduce<<<BSZ, 128>>>(en);
}

// round 17
// speedup vs baseline: 1.0118x; 1.0118x over previous
#include <cuda_runtime.h>
#include <cuda_fp16.h>
#include <math.h>
#include <stdint.h>

#define BSZ 32
#define LEN 8192
#define ROWS (BSZ*LEN)
#define NTILES (ROWS/64)     // 4096 tiles of 64 rows
#define MUGRID 148

// fp16-element strides (all == 4 mod 32 words -> conflict-free)
#define S1 136
#define S2 264
#define SQ 72
// smem byte offsets
#define OW2  69632
#define OWQ  103424
#define OPX0 112640
#define OPX1 130048
#define OPQ  147456
#define OPH  156672
#define OB1  190464
#define OB2  191488
#define OBQ  191744
#define SMEM_MU 192000

__device__ float g_mu[(size_t)ROWS * 64];
__device__ float g_epart[BSZ * 128];

// ---------------------------------------------------------------------------
__device__ __forceinline__ void mma16816h(float* c, const uint32_t* a,
                                          uint32_t b0, uint32_t b1)
{
    asm volatile(
        "mma.sync.aligned.m16n8k16.row.col.f32.f16.f16.f32 "
        "{%0,%1,%2,%3},{%4,%5,%6,%7},{%8,%9},{%0,%1,%2,%3};\n"
        : "+f"(c[0]), "+f"(c[1]), "+f"(c[2]), "+f"(c[3])
        : "r"(a[0]), "r"(a[1]), "r"(a[2]), "r"(a[3]), "r"(b0), "r"(b1));
}

__device__ __forceinline__ void ldsm4(uint32_t* d, uint32_t addr)
{
    asm volatile("ldmatrix.sync.aligned.m8n8.x4.shared.b16 {%0,%1,%2,%3}, [%4];"
        : "=r"(d[0]), "=r"(d[1]), "=r"(d[2]), "=r"(d[3]) : "r"(addr));
}

__device__ __forceinline__ uint32_t pack2h(float x0, float x1)
{
    __half2 h = __floats2half2_rn(x0, x1);
    return *(uint32_t*)&h;
}

__device__ __forceinline__ float tanh_fast(float x)
{
    float y;
    asm("tanh.approx.f32 %0, %1;" : "=f"(y) : "f"(x));
    return y;
}

__device__ __forceinline__ float softplus_fast(float m)
{
    return fmaxf(m, 0.f) + __logf(1.f + __expf(-fabsf(m)));
}

// ---------------------------------------------------------------------------
// Persistent mu kernel: 148 CTAs x 512 thr, 64-row tiles, fp16 MMA.
//   H = relu([A;B] @ W1h + b1); M = H @ W2h + b2; G = q @ Wqh + bq
//   mu = softplus(M) * (1 + 0.5*tanh(G))
// Stage1: 2m x 8n warps; stage2/gate: 4m x 4n. B via ldmatrix.x4.
// TWO syncs per tile: double-buffered X planes (parity) + dedicated q buffer.
//   phase A: stage1 on X[p]; prefetch q(t), X(t+G) to regs
//   S1 ; store H, q, X[p^1] ; S2
//   phase B: stage2 + gate + epilogue  -> next tile, no sync
// ---------------------------------------------------------------------------
__global__ void __launch_bounds__(512, 1) mu_kernel(
        const float* __restrict__ A, const float* __restrict__ Bm,
        const float* __restrict__ qp,
        const float* __restrict__ W1, const float* __restrict__ b1,
        const float* __restrict__ W2, const float* __restrict__ b2,
        const float* __restrict__ Wq, const float* __restrict__ bq)
{
    extern __shared__ char sm[];
    __half* sW1 = (__half*)sm;
    __half* sW2 = (__half*)(sm + OW2);
    __half* sWq = (__half*)(sm + OWQ);
    __half* pQ  = (__half*)(sm + OPQ);
    __half* pH  = (__half*)(sm + OPH);
    float* sB1 = (float*)(sm + OB1);
    float* sB2 = (float*)(sm + OB2);
    float* sBq = (float*)(sm + OBQ);

    const int tid = threadIdx.x, lane = tid & 31, wid = tid >> 5;
    const int wm = wid & 1, wn = wid >> 1;            // stage1: 2m x 8n
    const int wm2 = wid & 3, wn2 = wid >> 2;          // stage2/gate: 4m x 4n
    const int r = lane >> 2, c2 = lane & 3;
    const uint32_t smb = (uint32_t)__cvta_generic_to_shared(sm);

    // one-time fills (coalesced fp32 reads, fp16 convert)
    for (int i = tid; i < 256 * 128; i += 512) {
        int k = i >> 8, n = i & 255;                  // W1[k][n]
        sW1[n * S1 + k] = __float2half_rn(W1[i]);
    }
    for (int i = tid; i < 64 * 256; i += 512) {
        int k = i >> 6, n = i & 63;                   // W2[k][n]
        sW2[n * S2 + k] = __float2half_rn(W2[i]);
    }
    for (int i = tid; i < 64 * 64; i += 512) {
        int k = i >> 6, n = i & 63;                   // Wq[k][n]
        sWq[n * SQ + k] = __float2half_rn(Wq[i]);
    }
    if (tid < 256) sB1[tid] = b1[tid];
    if (tid < 64) { sB2[tid] = b2[tid]; sBq[tid] = bq[tid]; }

    // ldmatrix lane->address components
    const int lrow = (lane & 7) + ((lane >> 3) & 1) * 8;   // A-frag pattern
    const int lk   = (lane >> 4) * 8;
    const int brow = (lane & 7) + ((lane >> 4) << 3);      // B-frag pattern
    const int bk   = ((lane >> 3) & 1) << 3;
    const uint32_t pQs = smb + OPQ, pHs = smb + OPH;
    const uint32_t sW1s = smb, sW2s = smb + OW2, sWqs = smb + OWQ;
    const uint32_t pXs[2] = { smb + OPX0, smb + OPX1 };
    __half* const pXp[2] = { (__half*)(sm + OPX0), (__half*)(sm + OPX1) };

    // prologue: stage first tile's X into buffer 0
    {
        int t0 = blockIdx.x;
        if (t0 < NTILES) {
            const size_t row0 = (size_t)t0 * 64;
#pragma unroll
            for (int i = 0; i < 4; i++) {
                int e = i * 512 + tid;
                int row = e >> 5, kk = (e & 31) * 4;
                const float* src = (kk < 64) ? (A + (row0 + row) * 64 + kk)
                                             : (Bm + (row0 + row) * 64 + kk - 64);
                float4 v = *(const float4*)src;
                *(uint2*)(pXp[0] + row * S1 + kk) =
                    make_uint2(pack2h(v.x, v.y), pack2h(v.z, v.w));
            }
        }
    }
    __syncthreads();

    const int oc = (wn2 << 4) + (c2 << 1);                 // stage2/gate col base
    float b2v[2][2], bqv[2][2];
#pragma unroll
    for (int nt = 0; nt < 2; nt++) {
        b2v[nt][0] = sB2[oc + (nt << 3)]; b2v[nt][1] = sB2[oc + (nt << 3) + 1];
        bqv[nt][0] = sBq[oc + (nt << 3)]; bqv[nt][1] = sBq[oc + (nt << 3) + 1];
    }
    float b1v[4][2];
#pragma unroll
    for (int nt = 0; nt < 4; nt++) {
        int n0 = (wn << 5) + (nt << 3) + (c2 << 1);
        b1v[nt][0] = sB1[n0]; b1v[nt][1] = sB1[n0 + 1];
    }

    int p = 0;
    for (int t = blockIdx.x; t < NTILES; t += gridDim.x, p ^= 1) {
        const size_t row0 = (size_t)t * 64;
        const uint32_t pXcur = pXs[p];

        // prefetch q(t) (packed, 4 regs) — consumed in S1-S2 window
        uint32_t qr[4];
#pragma unroll
        for (int i = 0; i < 2; i++) {
            int e = i * 512 + tid;
            int row = e >> 4, kk = (e & 15) * 4;
            float4 v = *(const float4*)(qp + (row0 + row) * 64 + kk);
            qr[2 * i]     = pack2h(v.x, v.y);
            qr[2 * i + 1] = pack2h(v.z, v.w);
        }
        // prefetch X(t+G) (packed, 8 regs)
        uint32_t xr[8];
        {
            int tn = t + gridDim.x;
            if (tn < NTILES) {
                const size_t rown = (size_t)tn * 64;
#pragma unroll
                for (int i = 0; i < 4; i++) {
                    int e = i * 512 + tid;
                    int row = e >> 5, kk = (e & 31) * 4;
                    const float* src = (kk < 64) ? (A + (rown + row) * 64 + kk)
                                                 : (Bm + (rown + row) * 64 + kk - 64);
                    float4 v = *(const float4*)src;
                    xr[2 * i]     = pack2h(v.x, v.y);
                    xr[2 * i + 1] = pack2h(v.z, v.w);
                }
            }
        }

        // ---- phase A: stage 1: acc = X @ W1h (warp: 32 rows x 32 cols) ----
        float acc[2][4][4];
#pragma unroll
        for (int mt = 0; mt < 2; mt++)
#pragma unroll
            for (int nt = 0; nt < 4; nt++)
#pragma unroll
                for (int i = 0; i < 4; i++) acc[mt][nt][i] = 0.f;
#pragma unroll
        for (int ks = 0; ks < 8; ks++) {
            const int k0 = ks * 16;
            uint32_t ah[2][4], bw[8];
#pragma unroll
            for (int mt = 0; mt < 2; mt++) {
                uint32_t off = (uint32_t)((((wm << 5) + 16 * mt + lrow) * S1 + k0 + lk) * 2);
                ldsm4(ah[mt], pXcur + off);
            }
            ldsm4(bw,     sW1s + (uint32_t)((((wn << 5) + brow) * S1 + k0 + bk) * 2));
            ldsm4(bw + 4, sW1s + (uint32_t)((((wn << 5) + 16 + brow) * S1 + k0 + bk) * 2));
#pragma unroll
            for (int nt = 0; nt < 4; nt++)
#pragma unroll
                for (int mt = 0; mt < 2; mt++)
                    mma16816h(acc[mt][nt], ah[mt], bw[2 * nt], bw[2 * nt + 1]);
        }
        __syncthreads();                                  // S1

        // ---- store H (relu+bias), q, and next X into buffer p^1 ----
#pragma unroll
        for (int mt = 0; mt < 2; mt++)
#pragma unroll
            for (int nt = 0; nt < 4; nt++) {
                int cl = (wn << 5) + (nt << 3) + (c2 << 1);
                int rb = (wm << 5) + 16 * mt;
                float h0 = fmaxf(acc[mt][nt][0] + b1v[nt][0], 0.f);
                float h1 = fmaxf(acc[mt][nt][1] + b1v[nt][1], 0.f);
                *(uint32_t*)(pH + (rb + r) * S2 + cl) = pack2h(h0, h1);
                float h2 = fmaxf(acc[mt][nt][2] + b1v[nt][0], 0.f);
                float h3 = fmaxf(acc[mt][nt][3] + b1v[nt][1], 0.f);
                *(uint32_t*)(pH + (rb + 8 + r) * S2 + cl) = pack2h(h2, h3);
            }
#pragma unroll
        for (int i = 0; i < 2; i++) {
            int e = i * 512 + tid;
            int row = e >> 4, kk = (e & 15) * 4;
            *(uint2*)(pQ + row * SQ + kk) = make_uint2(qr[2 * i], qr[2 * i + 1]);
        }
        if (t + gridDim.x < NTILES) {
            __half* pXn = pXp[p ^ 1];
#pragma unroll
            for (int i = 0; i < 4; i++) {
                int e = i * 512 + tid;
                int row = e >> 5, kk = (e & 31) * 4;
                *(uint2*)(pXn + row * S1 + kk) = make_uint2(xr[2 * i], xr[2 * i + 1]);
            }
        }
        __syncthreads();                                  // S2

        // ---- phase B: stage 2: M = H @ W2h (warp: 16 rows x 16 cols) ----
        float acc2[2][4];
#pragma unroll
        for (int nt = 0; nt < 2; nt++)
#pragma unroll
            for (int i = 0; i < 4; i++) acc2[nt][i] = 0.f;
#pragma unroll
        for (int ks = 0; ks < 16; ks++) {
            const int k0 = ks * 16;
            uint32_t ah[4], bw[4];
            ldsm4(ah, pHs + (uint32_t)((((wm2 << 4) + lrow) * S2 + k0 + lk) * 2));
            ldsm4(bw, sW2s + (uint32_t)((((wn2 << 4) + brow) * S2 + k0 + bk) * 2));
            mma16816h(acc2[0], ah, bw[0], bw[1]);
            mma16816h(acc2[1], ah, bw[2], bw[3]);
        }

        // ---- gate: G = q @ Wqh (warp: 16 rows x 16 cols, K=64) ----
        float accg[2][4];
#pragma unroll
        for (int nt = 0; nt < 2; nt++)
#pragma unroll
            for (int i = 0; i < 4; i++) accg[nt][i] = 0.f;
#pragma unroll
        for (int ks = 0; ks < 4; ks++) {
            const int k0 = ks * 16;
            uint32_t ah[4], bw[4];
            ldsm4(ah, pQs + (uint32_t)((((wm2 << 4) + lrow) * SQ + k0 + lk) * 2));
            ldsm4(bw, sWqs + (uint32_t)((((wn2 << 4) + brow) * SQ + k0 + bk) * 2));
            mma16816h(accg[0], ah, bw[0], bw[1]);
            mma16816h(accg[1], ah, bw[2], bw[3]);
        }

        // ---- epilogue: mu = softplus(M+b2) * (1 + 0.5*tanh(G+bq)) ----
#pragma unroll
        for (int nt = 0; nt < 2; nt++) {
            int col = oc + (nt << 3);
            int row = (wm2 << 4) + r;
            float m0 = acc2[nt][0] + b2v[nt][0], m1 = acc2[nt][1] + b2v[nt][1];
            float g0 = tanh_fast(accg[nt][0] + bqv[nt][0]);
            float g1 = tanh_fast(accg[nt][1] + bqv[nt][1]);
            *(float2*)&g_mu[(row0 + row) * 64 + col] =
                make_float2(softplus_fast(m0) * (1.f + 0.5f * g0),
                            softplus_fast(m1) * (1.f + 0.5f * g1));
            float m2 = acc2[nt][2] + b2v[nt][0], m3 = acc2[nt][3] + b2v[nt][1];
            float g2 = tanh_fast(accg[nt][2] + bqv[nt][0]);
            float g3 = tanh_fast(accg[nt][3] + bqv[nt][1]);
            *(float2*)&g_mu[(row0 + row + 8) * 64 + col] =
                make_float2(softplus_fast(m2) * (1.f + 0.5f * g2),
                            softplus_fast(m3) * (1.f + 0.5f * g3));
        }
        // no sync: next tile's S1 protects pH/pQ/pX overwrites
    }
}

// ---------------------------------------------------------------------------
// Iteration kernel: 10 rows/thread, TL=64 interior, halo 8, 2 blocks/SM.
// smooth(x)[l] = 0.9*x[l] + 0.05*(x[l-1]+x[l+1]);  D scaled by (1-0.3*mu).
// ---------------------------------------------------------------------------
__global__ void __launch_bounds__(512, 2) iter_kernel(
        const float* __restrict__ A, const float* __restrict__ Bm,
        float* __restrict__ hA, float* __restrict__ hB)
{
    __shared__ float sme[2][4][8][64];
    const int tid = threadIdx.x;
    const int c = tid & 63;
    const int j = tid >> 6;
    const int b = blockIdx.y;
    const int lbase = blockIdx.x * 64 - 8;
    const size_t base = ((size_t)b << 13);

    float D[10], S[10], MU[10];
#pragma unroll
    for (int rr = 0; rr < 10; rr++) {
        int l = (lbase + j * 10 + rr) & (LEN - 1);
        size_t g = (base + l) * 64 + c;
        float a = A[g], bb = Bm[g];
        D[rr] = a - bb;
        S[rr] = a + bb;
        MU[rr] = g_mu[g];
    }

#pragma unroll
    for (int k = 0; k < 6; k++) {
        const int p = k & 1;
        sme[p][0][j][c] = (1.f - 0.3f * MU[0]) * D[0];
        sme[p][1][j][c] = (1.f - 0.3f * MU[9]) * D[9];
        sme[p][2][j][c] = S[0];
        sme[p][3][j][c] = S[9];
        __syncthreads();
        float gylo = (j > 0) ? sme[p][1][j - 1][c] : 0.f;
        float gyhi = (j < 7) ? sme[p][0][j + 1][c] : 0.f;
        float gslo = (j > 0) ? sme[p][3][j - 1][c] : 0.f;
        float gshi = (j < 7) ? sme[p][2][j + 1][c] : 0.f;

        float yprev = gylo, sprev = gslo;
#pragma unroll
        for (int rr = 0; rr < 10; rr++) {
            float ycur  = (1.f - 0.3f * MU[rr]) * D[rr];
            float ynext = (rr < 9) ? (1.f - 0.3f * MU[rr + 1]) * D[rr + 1] : gyhi;
            float scur  = S[rr];
            float snext = (rr < 9) ? S[rr + 1] : gshi;
            D[rr] = 0.9f * ycur + 0.05f * (yprev + ynext);
            S[rr] = 0.9f * scur + 0.05f * (sprev + snext);
            yprev = ycur;
            sprev = scur;
        }
    }

    float esum = 0.f;
#pragma unroll
    for (int rr = 0; rr < 10; rr++) {
        int gidx = j * 10 + rr;
        if (gidx >= 8 && gidx < 72) {
            int l = blockIdx.x * 64 + (gidx - 8);
            size_t g = (base + l) * 64 + c;
            hA[g] = 0.5f * (S[rr] + D[rr]);
            hB[g] = 0.5f * (S[rr] - D[rr]);
            esum += 0.5f * MU[rr] * D[rr] * D[rr];
        }
    }

#pragma unroll
    for (int o = 16; o > 0; o >>= 1)
        esum += __shfl_xor_sync(0xffffffffu, esum, o);
    __shared__ float sred[16];
    if ((tid & 31) == 0) sred[tid >> 5] = esum;
    __syncthreads();
    if (tid == 0) {
        float tt = 0.f;
#pragma unroll
        for (int w = 0; w < 16; w++) tt += sred[w];
        g_epart[b * 128 + blockIdx.x] = tt;
    }
}

// ---------------------------------------------------------------------------
__global__ void __launch_bounds__(128) energy_reduce(float* __restrict__ energy)
{
    const int b = blockIdx.x;
    const int tid = threadIdx.x;
    float v = g_epart[b * 128 + tid];
#pragma unroll
    for (int o = 16; o > 0; o >>= 1)
        v += __shfl_xor_sync(0xffffffffu, v, o);
    __shared__ float s[4];
    if ((tid & 31) == 0) s[tid >> 5] = v;
    __syncthreads();
    if (tid == 0) energy[b] = s[0] + s[1] + s[2] + s[3];
}

// ---------------------------------------------------------------------------
extern "C" void kernel_launch(void* const* d_in, const int* in_sizes, int n_in,
                              void* d_out, int out_size)
{
    const float* A  = (const float*)d_in[0];
    const float* Bm = (const float*)d_in[1];
    const float* q  = (const float*)d_in[2];
    const float* W1 = (const float*)d_in[3];
    const float* b1 = (const float*)d_in[4];
    const float* W2 = (const float*)d_in[5];
    const float* b2 = (const float*)d_in[6];
    const float* Wq = (const float*)d_in[7];
    const float* bq = (const float*)d_in[8];

    float* out = (float*)d_out;
    float* hA = out;
    float* hB = out + (size_t)ROWS * 64;
    float* en = out + 2 * (size_t)ROWS * 64;

    static int attr_set = 0;
    if (!attr_set) {
        cudaFuncSetAttribute(mu_kernel,
            cudaFuncAttributeMaxDynamicSharedMemorySize, SMEM_MU);
        attr_set = 1;
    }
    mu_kernel<<<MUGRID, 512, SMEM_MU>>>(A, Bm, q, W1, b1, W2, b2, Wq, bq);

    iter_kernel<<<dim3(LEN / 64, BSZ), 512>>>(A, Bm, hA, hB);

    energy_reduce<<<BSZ, 128>>>(en);
}